// round 14
// baseline (speedup 1.0000x reference)
#include <cuda_runtime.h>
#include <cuda_bf16.h>

#define NGAUSS 2048
#define NCLASS 17
#define NFIELD 26   // 3 mean + 6 (-0.5*covinv, off-diag pre-doubled) + 17 opacity*semantics
#define BATCH  32
#define NBINS  100  // 10x10 supertiles of 10x10 voxels

// Field-major gaussian data: g_gd[field][gauss]
__device__ float g_gd[NFIELD][NGAUSS];
// Per-supertile candidate shortlist (sorted ascending, deterministic)
__device__ unsigned short g_bin_list[NBINS][NGAUSS];
__device__ int g_bin_cnt[NBINS];

__device__ __forceinline__ float softplus_ref(float x) {
    // jax.nn.softplus = max(x,0) + log1p(exp(-|x|))
    return fmaxf(x, 0.0f) + log1pf(expf(-fabsf(x)));
}

__global__ void prep_kernel(const float* __restrict__ props) {
    int n = blockIdx.x * blockDim.x + threadIdx.x;
    if (n >= NGAUSS) return;
    const float* p = props + n * (11 + NCLASS);

    float mx = p[0], my = p[1], mz = p[2];

    float s0 = fmaxf(softplus_ref(p[3]), 1e-4f);
    float s1 = fmaxf(softplus_ref(p[4]), 1e-4f);
    float s2 = fmaxf(softplus_ref(p[5]), 1e-4f);
    float i0 = 1.0f / fmaxf(s0 * s0, 1e-8f);
    float i1 = 1.0f / fmaxf(s1 * s1, 1e-8f);
    float i2 = 1.0f / fmaxf(s2 * s2, 1e-8f);

    float qw = p[6], qx = p[7], qy = p[8], qz = p[9];
    float qn = sqrtf(qw*qw + qx*qx + qy*qy + qz*qz);
    qn = fmaxf(qn, 1e-8f);
    float inv = 1.0f / qn;
    qw *= inv; qx *= inv; qy *= inv; qz *= inv;

    float R00 = 1.0f - 2.0f*(qy*qy + qz*qz);
    float R01 = 2.0f*(qx*qy - qw*qz);
    float R02 = 2.0f*(qx*qz + qw*qy);
    float R10 = 2.0f*(qx*qy + qw*qz);
    float R11 = 1.0f - 2.0f*(qx*qx + qz*qz);
    float R12 = 2.0f*(qy*qz - qw*qx);
    float R20 = 2.0f*(qx*qz - qw*qy);
    float R21 = 2.0f*(qy*qz + qw*qx);
    float R22 = 1.0f - 2.0f*(qx*qx + qy*qy);

    // cov_inv[i][k] = sum_j R[i][j] * inv_s2[j] * R[k][j]
    float a00 = R00*R00*i0 + R01*R01*i1 + R02*R02*i2;
    float a11 = R10*R10*i0 + R11*R11*i1 + R12*R12*i2;
    float a22 = R20*R20*i0 + R21*R21*i1 + R22*R22*i2;
    float a01 = R00*R10*i0 + R01*R11*i1 + R02*R12*i2;
    float a02 = R00*R20*i0 + R01*R21*i1 + R02*R22*i2;
    float a12 = R10*R20*i0 + R11*R21*i1 + R12*R22*i2;

    float opac = 1.0f / (1.0f + expf(-p[10]));

    g_gd[0][n] = mx;
    g_gd[1][n] = my;
    g_gd[2][n] = mz;
    // fold -0.5 so exp argument = dot product directly
    g_gd[3][n] = -0.5f * a00;
    g_gd[4][n] = -0.5f * a11;
    g_gd[5][n] = -0.5f * a22;
    g_gd[6][n] = -a01;      // -0.5 * 2*a01
    g_gd[7][n] = -a02;
    g_gd[8][n] = -a12;
#pragma unroll
    for (int c = 0; c < NCLASS; c++)
        g_gd[9 + c][n] = opac * p[11 + c];
}

// Coarse cull: one CTA = 10x10-voxel supertile; writes sorted shortlist to global.
__global__ __launch_bounds__(128) void bin_kernel() {
    __shared__ unsigned short s_seg[4][512];
    __shared__ int s_wcnt[4];

    const int tid  = threadIdx.x;
    const int lane = tid & 31;
    const int wid  = tid >> 5;
    const int sx = blockIdx.x, sy = blockIdx.y;

    const float step = 80.0f / 99.0f;
    const float hw = 4.5f * step + 0.01f;    // supertile half-width, inflated
    const float cx = -40.0f + ((float)(sx * 10) + 4.5f) * step;
    const float cy = -40.0f + ((float)(sy * 10) + 4.5f) * step;

    {
        int wbase = wid * 512;
        int wcnt = 0;
        unsigned lmask = (1u << lane) - 1u;
#pragma unroll 4
        for (int it = 0; it < 16; it++) {
            int g = wbase + it * 32 + lane;
            float dxm = fmaxf(fabsf(g_gd[0][g] - cx) - hw, 0.0f);
            float dym = fmaxf(fabsf(g_gd[1][g] - cy) - hw, 0.0f);
            bool keep = (dxm * dxm + dym * dym) < 16.0001f;  // R^2 = 16
            unsigned b = __ballot_sync(0xffffffffu, keep);
            if (keep)
                s_seg[wid][wcnt + __popc(b & lmask)] = (unsigned short)g;
            wcnt += __popc(b);
        }
        if (lane == 0) s_wcnt[wid] = wcnt;
    }
    __syncthreads();

    int off = 0, total = 0;
#pragma unroll
    for (int w = 0; w < 4; w++) {
        if (w < wid) off += s_wcnt[w];
        total += s_wcnt[w];
    }
    const int bin = sx * 10 + sy;
    {
        int wcnt = s_wcnt[wid];
        for (int j = lane; j < wcnt; j += 32)
            g_bin_list[bin][off + j] = s_seg[wid][j];
    }
    if (tid == 0) g_bin_cnt[bin] = total;
}

// One CTA = 2x2 xy voxel tile, all 8 z levels = 32 voxels.
// 128 threads: 4 threads per voxel, candidates split by j%4, butterfly reduce.
// Fine cull runs over the supertile shortlist (typically 1 ballot iteration).
__global__ __launch_bounds__(128) void splat_kernel(
    const float* __restrict__ vc,   // voxel_coords [80000,3]
    float* __restrict__ out)        // [80000,17]
{
    __shared__ unsigned short s_seg[4][512];   // per-warp cull segments
    __shared__ unsigned short s_idx[NGAUSS];   // compacted candidate list
    __shared__ int s_wcnt[4];
    __shared__ float s_d[NFIELD][BATCH];

    const int tid  = threadIdx.x;
    const int lane = tid & 31;
    const int wid  = tid >> 5;
    const int tx = blockIdx.x, ty = blockIdx.y;

    // -------- Phase A: fine cull over supertile shortlist --------
    const float step = 80.0f / 99.0f;
    const float hw = 0.5f * step + 0.01f;    // 2x2 tile half-width, inflated
    const float cx = -40.0f + ((float)(tx * 2) + 0.5f) * step;
    const float cy = -40.0f + ((float)(ty * 2) + 0.5f) * step;

    const int bin = (tx / 5) * 10 + (ty / 5);
    const int cnt = g_bin_cnt[bin];
    const unsigned short* __restrict__ blist = g_bin_list[bin];

    {
        int wcnt = 0;
        unsigned lmask = (1u << lane) - 1u;
        for (int c0 = 0; c0 < cnt; c0 += 128) {
            int li = c0 + wid * 32 + lane;
            bool inb = (li < cnt);
            int g = inb ? (int)blist[li] : 0;
            bool keep = false;
            if (inb) {
                float dxm = fmaxf(fabsf(g_gd[0][g] - cx) - hw, 0.0f);
                float dym = fmaxf(fabsf(g_gd[1][g] - cy) - hw, 0.0f);
                keep = (dxm * dxm + dym * dym) < 16.0001f;  // R^2 = 16
            }
            unsigned b = __ballot_sync(0xffffffffu, keep);
            if (keep)
                s_seg[wid][wcnt + __popc(b & lmask)] = (unsigned short)g;
            wcnt += __popc(b);
        }
        if (lane == 0) s_wcnt[wid] = wcnt;
    }
    __syncthreads();

    int off = 0, total = 0;
#pragma unroll
    for (int w = 0; w < 4; w++) {
        if (w < wid) off += s_wcnt[w];
        total += s_wcnt[w];
    }
    // compact per-warp segments into one candidate list (deterministic order)
    {
        int wcnt = s_wcnt[wid];
        for (int j = lane; j < wcnt; j += 32)
            s_idx[off + j] = s_seg[wid][j];
    }
    __syncthreads();

    // -------- Per-voxel setup (4 threads per voxel) --------
    const int r  = tid & 3;          // candidate-slice id
    const int vl = tid >> 2;         // local voxel 0..31
    const int iz = vl & 7;
    const int ly = (vl >> 3) & 1;
    const int lx = vl >> 4;
    const int ix = tx * 2 + lx;
    const int iy = ty * 2 + ly;
    const int v  = (ix * 100 + iy) * 8 + iz;

    const float vx = __ldg(&vc[3 * v + 0]);
    const float vy = __ldg(&vc[3 * v + 1]);
    const float vz = __ldg(&vc[3 * v + 2]);

    float acc[NCLASS];
#pragma unroll
    for (int c = 0; c < NCLASS; c++) acc[c] = 0.0f;
    if (r == 0) {
        // empty gaussian: center (0,0,2.2), -0.5*inv = (-3.125e-4,-3.125e-4,-0.048828125)
        float dez = vz - 2.2f;
        float me = vx * vx * (-3.125e-4f)
                 + vy * vy * (-3.125e-4f)
                 + dez * dez * (-0.048828125f);
        acc[0] = 0.5f * __expf(me);   // 0.1 * exp * 5.0
    }

    // -------- Phase B: batched candidate processing --------
    for (int base = 0; base < total; base += BATCH) {
        int cnt2 = min(BATCH, total - base);
        // stage SoA into smem (gather via index list)
        for (int t = tid; t < NFIELD * BATCH; t += 128) {
            int f = t >> 5;          // /BATCH
            int j = t & (BATCH - 1);
            if (j < cnt2) s_d[f][j] = g_gd[f][s_idx[base + j]];
        }
        __syncthreads();

        for (int j = r; j < cnt2; j += 4) {
            float dx = vx - s_d[0][j];
            float dy = vy - s_d[1][j];
            float dz = vz - s_d[2][j];
            float dsq = dx * dx + dy * dy + dz * dz;
            if (dsq < 16.0f) {
                float m = s_d[3][j] * (dx * dx)
                        + s_d[4][j] * (dy * dy)
                        + s_d[5][j] * (dz * dz)
                        + s_d[6][j] * (dx * dy)
                        + s_d[7][j] * (dx * dz)
                        + s_d[8][j] * (dy * dz);
                float w = __expf(m);
#pragma unroll
                for (int c = 0; c < NCLASS; c++)
                    acc[c] += w * s_d[9 + c][j];
            }
        }
        __syncthreads();
    }

    // -------- Butterfly reduce across the 4 threads of each voxel --------
#pragma unroll
    for (int c = 0; c < NCLASS; c++) {
        acc[c] += __shfl_xor_sync(0xffffffffu, acc[c], 1);
        acc[c] += __shfl_xor_sync(0xffffffffu, acc[c], 2);
    }

    float* o = out + (size_t)v * NCLASS;
    for (int c = r; c < NCLASS; c += 4) o[c] = acc[c];
}

extern "C" void kernel_launch(void* const* d_in, const int* in_sizes, int n_in,
                              void* d_out, int out_size) {
    const float* props = (const float*)d_in[0];   // [1, 2048, 28]
    const float* vc    = (const float*)d_in[1];   // [80000, 3]
    float* out = (float*)d_out;                   // [1,100,100,8,17] f32

    prep_kernel<<<(NGAUSS + 255) / 256, 256>>>(props);
    bin_kernel<<<dim3(10, 10), 128>>>();
    dim3 grid(50, 50);
    splat_kernel<<<grid, 128>>>(vc, out);
}

// round 16
// speedup vs baseline: 1.0923x; 1.0923x over previous
#include <cuda_runtime.h>
#include <cuda_bf16.h>

#define NGAUSS 2048
#define NCLASS 17
#define NFIELD 26   // 3 mean + 6 (-0.5*covinv, off-diag pre-doubled) + 17 opacity*semantics
#define BATCH  32
#define NBINS  100  // 10x10 supertiles of 10x10 voxels
#define PROPS_STRIDE 28

// Field-major gaussian data: g_gd[field][gauss]
__device__ float g_gd[NFIELD][NGAUSS];
// Per-supertile candidate shortlist (sorted ascending, deterministic)
__device__ unsigned short g_bin_list[NBINS][NGAUSS];
__device__ int g_bin_cnt[NBINS];

__device__ __forceinline__ float softplus_ref(float x) {
    // jax.nn.softplus = max(x,0) + log1p(exp(-|x|))
    return fmaxf(x, 0.0f) + log1pf(expf(-fabsf(x)));
}

// Fused kernel: CTAs 0..7 = prep (256 gaussians each, smem-staged coalesced loads),
// CTAs 8..107 = coarse cull for one 10x10-voxel supertile (reads RAW means from
// props — no dependency on the prep CTAs).
__global__ __launch_bounds__(256) void prep_bin_kernel(const float* __restrict__ props) {
    __shared__ float s_buf[256 * PROPS_STRIDE];   // 28 KB, reused by both paths

    const int tid  = threadIdx.x;
    const int lane = tid & 31;
    const int wid  = tid >> 5;

    if (blockIdx.x < 8) {
        // ---------------- PREP path ----------------
        const int base = blockIdx.x * 256;
        // coalesced bulk copy of this chunk of props into smem
        const float* src = props + (size_t)base * PROPS_STRIDE;
        for (int i = tid; i < 256 * PROPS_STRIDE; i += 256)
            s_buf[i] = src[i];
        __syncthreads();

        const int n = base + tid;
        const float* p = s_buf + tid * PROPS_STRIDE;

        float mx = p[0], my = p[1], mz = p[2];

        float s0 = fmaxf(softplus_ref(p[3]), 1e-4f);
        float s1 = fmaxf(softplus_ref(p[4]), 1e-4f);
        float s2 = fmaxf(softplus_ref(p[5]), 1e-4f);
        float i0 = 1.0f / fmaxf(s0 * s0, 1e-8f);
        float i1 = 1.0f / fmaxf(s1 * s1, 1e-8f);
        float i2 = 1.0f / fmaxf(s2 * s2, 1e-8f);

        float qw = p[6], qx = p[7], qy = p[8], qz = p[9];
        float qn = sqrtf(qw*qw + qx*qx + qy*qy + qz*qz);
        qn = fmaxf(qn, 1e-8f);
        float inv = 1.0f / qn;
        qw *= inv; qx *= inv; qy *= inv; qz *= inv;

        float R00 = 1.0f - 2.0f*(qy*qy + qz*qz);
        float R01 = 2.0f*(qx*qy - qw*qz);
        float R02 = 2.0f*(qx*qz + qw*qy);
        float R10 = 2.0f*(qx*qy + qw*qz);
        float R11 = 1.0f - 2.0f*(qx*qx + qz*qz);
        float R12 = 2.0f*(qy*qz - qw*qx);
        float R20 = 2.0f*(qx*qz - qw*qy);
        float R21 = 2.0f*(qy*qz + qw*qx);
        float R22 = 1.0f - 2.0f*(qx*qx + qy*qy);

        // cov_inv[i][k] = sum_j R[i][j] * inv_s2[j] * R[k][j]
        float a00 = R00*R00*i0 + R01*R01*i1 + R02*R02*i2;
        float a11 = R10*R10*i0 + R11*R11*i1 + R12*R12*i2;
        float a22 = R20*R20*i0 + R21*R21*i1 + R22*R22*i2;
        float a01 = R00*R10*i0 + R01*R11*i1 + R02*R12*i2;
        float a02 = R00*R20*i0 + R01*R21*i1 + R02*R22*i2;
        float a12 = R10*R20*i0 + R11*R21*i1 + R12*R22*i2;

        float opac = 1.0f / (1.0f + expf(-p[10]));

        g_gd[0][n] = mx;
        g_gd[1][n] = my;
        g_gd[2][n] = mz;
        // fold -0.5 so exp argument = dot product directly
        g_gd[3][n] = -0.5f * a00;
        g_gd[4][n] = -0.5f * a11;
        g_gd[5][n] = -0.5f * a22;
        g_gd[6][n] = -a01;      // -0.5 * 2*a01
        g_gd[7][n] = -a02;
        g_gd[8][n] = -a12;
#pragma unroll
        for (int c = 0; c < NCLASS; c++)
            g_gd[9 + c][n] = opac * p[11 + c];
    } else {
        // ---------------- BIN path (coarse cull, raw means) ----------------
        unsigned short* s_seg = (unsigned short*)s_buf;       // [8][256]
        int* s_wcnt = (int*)(s_buf + 8 * 256 / 2 + 64);       // after segs, padded

        const int b  = blockIdx.x - 8;
        const int sx = b / 10, sy = b % 10;

        const float step = 80.0f / 99.0f;
        const float hw = 4.5f * step + 0.01f;    // supertile half-width, inflated
        const float cx = -40.0f + ((float)(sx * 10) + 4.5f) * step;
        const float cy = -40.0f + ((float)(sy * 10) + 4.5f) * step;

        {
            int wbase = wid * 256;
            int wcnt = 0;
            unsigned lmask = (1u << lane) - 1u;
#pragma unroll
            for (int it = 0; it < 8; it++) {
                int g = wbase + it * 32 + lane;
                const float2 m2 = *(const float2*)(props + (size_t)g * PROPS_STRIDE);
                float dxm = fmaxf(fabsf(m2.x - cx) - hw, 0.0f);
                float dym = fmaxf(fabsf(m2.y - cy) - hw, 0.0f);
                bool keep = (dxm * dxm + dym * dym) < 16.0001f;  // R^2 = 16
                unsigned bb = __ballot_sync(0xffffffffu, keep);
                if (keep)
                    s_seg[wid * 256 + wcnt + __popc(bb & lmask)] = (unsigned short)g;
                wcnt += __popc(bb);
            }
            if (lane == 0) s_wcnt[wid] = wcnt;
        }
        __syncthreads();

        int off = 0, total = 0;
#pragma unroll
        for (int w = 0; w < 8; w++) {
            if (w < wid) off += s_wcnt[w];
            total += s_wcnt[w];
        }
        {
            int wcnt = s_wcnt[wid];
            for (int j = lane; j < wcnt; j += 32)
                g_bin_list[b][off + j] = s_seg[wid * 256 + j];
        }
        if (tid == 0) g_bin_cnt[b] = total;
    }
}

// One CTA = 2x2 xy voxel tile, all 8 z levels = 32 voxels.
// 128 threads: 4 threads per voxel, candidates split by j%4, butterfly reduce.
// Fine cull runs over the supertile shortlist (typically 1 ballot iteration).
__global__ __launch_bounds__(128) void splat_kernel(
    const float* __restrict__ vc,   // voxel_coords [80000,3]
    float* __restrict__ out)        // [80000,17]
{
    __shared__ unsigned short s_seg[4][512];   // per-warp cull segments
    __shared__ unsigned short s_idx[NGAUSS];   // compacted candidate list
    __shared__ int s_wcnt[4];
    __shared__ float s_d[NFIELD][BATCH];

    const int tid  = threadIdx.x;
    const int lane = tid & 31;
    const int wid  = tid >> 5;
    const int tx = blockIdx.x, ty = blockIdx.y;

    // -------- Phase A: fine cull over supertile shortlist --------
    const float step = 80.0f / 99.0f;
    const float hw = 0.5f * step + 0.01f;    // 2x2 tile half-width, inflated
    const float cx = -40.0f + ((float)(tx * 2) + 0.5f) * step;
    const float cy = -40.0f + ((float)(ty * 2) + 0.5f) * step;

    const int bin = (tx / 5) * 10 + (ty / 5);
    const int cnt = g_bin_cnt[bin];
    const unsigned short* __restrict__ blist = g_bin_list[bin];

    {
        int wcnt = 0;
        unsigned lmask = (1u << lane) - 1u;
        for (int c0 = 0; c0 < cnt; c0 += 128) {
            int li = c0 + wid * 32 + lane;
            bool inb = (li < cnt);
            int g = inb ? (int)blist[li] : 0;
            bool keep = false;
            if (inb) {
                float dxm = fmaxf(fabsf(g_gd[0][g] - cx) - hw, 0.0f);
                float dym = fmaxf(fabsf(g_gd[1][g] - cy) - hw, 0.0f);
                keep = (dxm * dxm + dym * dym) < 16.0001f;  // R^2 = 16
            }
            unsigned b = __ballot_sync(0xffffffffu, keep);
            if (keep)
                s_seg[wid][wcnt + __popc(b & lmask)] = (unsigned short)g;
            wcnt += __popc(b);
        }
        if (lane == 0) s_wcnt[wid] = wcnt;
    }
    __syncthreads();

    int off = 0, total = 0;
#pragma unroll
    for (int w = 0; w < 4; w++) {
        if (w < wid) off += s_wcnt[w];
        total += s_wcnt[w];
    }
    // compact per-warp segments into one candidate list (deterministic order)
    {
        int wcnt = s_wcnt[wid];
        for (int j = lane; j < wcnt; j += 32)
            s_idx[off + j] = s_seg[wid][j];
    }
    __syncthreads();

    // -------- Per-voxel setup (4 threads per voxel) --------
    const int r  = tid & 3;          // candidate-slice id
    const int vl = tid >> 2;         // local voxel 0..31
    const int iz = vl & 7;
    const int ly = (vl >> 3) & 1;
    const int lx = vl >> 4;
    const int ix = tx * 2 + lx;
    const int iy = ty * 2 + ly;
    const int v  = (ix * 100 + iy) * 8 + iz;

    const float vx = __ldg(&vc[3 * v + 0]);
    const float vy = __ldg(&vc[3 * v + 1]);
    const float vz = __ldg(&vc[3 * v + 2]);

    float acc[NCLASS];
#pragma unroll
    for (int c = 0; c < NCLASS; c++) acc[c] = 0.0f;
    if (r == 0) {
        // empty gaussian: center (0,0,2.2), -0.5*inv = (-3.125e-4,-3.125e-4,-0.048828125)
        float dez = vz - 2.2f;
        float me = vx * vx * (-3.125e-4f)
                 + vy * vy * (-3.125e-4f)
                 + dez * dez * (-0.048828125f);
        acc[0] = 0.5f * __expf(me);   // 0.1 * exp * 5.0
    }

    // -------- Phase B: batched candidate processing --------
    for (int base = 0; base < total; base += BATCH) {
        int cnt2 = min(BATCH, total - base);
        // stage SoA into smem (gather via index list)
        for (int t = tid; t < NFIELD * BATCH; t += 128) {
            int f = t >> 5;          // /BATCH
            int j = t & (BATCH - 1);
            if (j < cnt2) s_d[f][j] = g_gd[f][s_idx[base + j]];
        }
        __syncthreads();

        for (int j = r; j < cnt2; j += 4) {
            float dx = vx - s_d[0][j];
            float dy = vy - s_d[1][j];
            float dz = vz - s_d[2][j];
            float dsq = dx * dx + dy * dy + dz * dz;
            if (dsq < 16.0f) {
                float m = s_d[3][j] * (dx * dx)
                        + s_d[4][j] * (dy * dy)
                        + s_d[5][j] * (dz * dz)
                        + s_d[6][j] * (dx * dy)
                        + s_d[7][j] * (dx * dz)
                        + s_d[8][j] * (dy * dz);
                float w = __expf(m);
#pragma unroll
                for (int c = 0; c < NCLASS; c++)
                    acc[c] += w * s_d[9 + c][j];
            }
        }
        __syncthreads();
    }

    // -------- Butterfly reduce across the 4 threads of each voxel --------
#pragma unroll
    for (int c = 0; c < NCLASS; c++) {
        acc[c] += __shfl_xor_sync(0xffffffffu, acc[c], 1);
        acc[c] += __shfl_xor_sync(0xffffffffu, acc[c], 2);
    }

    float* o = out + (size_t)v * NCLASS;
    for (int c = r; c < NCLASS; c += 4) o[c] = acc[c];
}

extern "C" void kernel_launch(void* const* d_in, const int* in_sizes, int n_in,
                              void* d_out, int out_size) {
    const float* props = (const float*)d_in[0];   // [1, 2048, 28]
    const float* vc    = (const float*)d_in[1];   // [80000, 3]
    float* out = (float*)d_out;                   // [1,100,100,8,17] f32

    prep_bin_kernel<<<108, 256>>>(props);
    dim3 grid(50, 50);
    splat_kernel<<<grid, 128>>>(vc, out);
}